// round 2
// baseline (speedup 1.0000x reference)
#include <cuda_runtime.h>

#define T_DIM 512
#define TPB   256
#define HALO  4
#define N_STEPS 5

__device__ __forceinline__ float sgnf(float x) {
    return (x > 0.0f) ? 1.0f : ((x < 0.0f) ? -1.0f : 0.0f);
}

__device__ __forceinline__ float rescale_f(float x) {
    const float EPS = 1e-3f;
    return sgnf(x) * (sqrtf(fabsf(x) + 1.0f) - 1.0f) + EPS * x;
}

__device__ __forceinline__ float inv_rescale_f(float x) {
    const float EPS = 1e-3f;
    float sqrt_arg = 1.0f + 4.0f * EPS * (fabsf(x) + 1.0f + EPS);
    float r = (sqrtf(sqrt_arg) - 1.0f) / (2.0f * EPS);
    return sgnf(x) * (r * r - 1.0f);
}

__global__ __launch_bounds__(TPB, 8)
void nstep_qloss_kernel(const float* __restrict__ cq,
                        const float* __restrict__ nq,
                        const float* __restrict__ logp,
                        const float* __restrict__ rw,
                        const float* __restrict__ done,
                        const float* __restrict__ mask,
                        float* __restrict__ out)
{
    __shared__ float4 s_mr[TPB + HALO];   // mask * reward
    __shared__ float4 s_nq[TPB + HALO];   // m*(1-d) * inv_rescale(next_q)
    __shared__ float  s_lp[TPB + HALO];   // (1/3) * m*(1-d) * log_p

    const float GAMMA = 0.997f;
    const float LN_GAMMA = -0.003004509021390342f; // ln(0.997)

    const int b  = blockIdx.x;
    const int t0 = blockIdx.y * TPB;
    const int lt = threadIdx.x;
    const int t  = t0 + lt;
    const long bt = (long)b * T_DIM + t;

    // ---- hoist ALL global loads up front (max MLP before barrier) ----
    float4 c4  = ((const float4*)cq)[bt];
    float  m   = mask[bt];
    float  d   = done[bt];
    float  lpv = logp[bt];
    float4 r4  = ((const float4*)rw)[bt];
    float4 n4  = ((const float4*)nq)[bt];

    // halo loads (threads 0..HALO-1 fetch t0+TPB .. t0+TPB+HALO-1)
    float hm = 0.f, hd = 0.f, hlp = 0.f;
    float4 hr4 = make_float4(0.f, 0.f, 0.f, 0.f);
    float4 hn4 = make_float4(0.f, 0.f, 0.f, 0.f);
    const int ht = t0 + TPB + lt;
    const bool do_halo = (lt < HALO) && (ht < T_DIM);
    if (do_halo) {
        long hbt = (long)b * T_DIM + ht;
        hm  = mask[hbt];
        hd  = done[hbt];
        hlp = logp[hbt];
        hr4 = ((const float4*)rw)[hbt];
        hn4 = ((const float4*)nq)[hbt];
    }

    float md = m * (1.0f - d);
    s_lp[lt] = (1.0f / 3.0f) * md * lpv;
    s_mr[lt] = make_float4(m * r4.x, m * r4.y, m * r4.z, m * r4.w);
    s_nq[lt] = make_float4(md * inv_rescale_f(n4.x),
                           md * inv_rescale_f(n4.y),
                           md * inv_rescale_f(n4.z),
                           md * inv_rescale_f(n4.w));
    if (lt < HALO) {
        float hmd = hm * (1.0f - hd);
        s_lp[TPB + lt] = (1.0f / 3.0f) * hmd * hlp;
        s_mr[TPB + lt] = make_float4(hm * hr4.x, hm * hr4.y, hm * hr4.z, hm * hr4.w);
        s_nq[TPB + lt] = make_float4(hmd * inv_rescale_f(hn4.x),
                                     hmd * inv_rescale_f(hn4.y),
                                     hmd * inv_rescale_f(hn4.z),
                                     hmd * inv_rescale_f(hn4.w));
    }
    __syncthreads();

    // windowed sums over n = 0..4 (zero-padded halo handles the T edge)
    float rs0 = 0.f, rs1 = 0.f, rs2 = 0.f, rs3 = 0.f;
    float lps = 0.f;   // sum gamma^(n+1) * lp[t+n]
    float g = 1.0f;
    #pragma unroll
    for (int n = 0; n < N_STEPS; n++) {
        float4 v = s_mr[lt + n];
        rs0 += g * v.x;
        rs1 += g * v.y;
        rs2 += g * v.z;
        rs3 += g * v.w;
        lps += g * GAMMA * s_lp[lt + n];
        g *= GAMMA;
    }

    // idx = min(T-1, t + 4); local clamp works because lt+4 <= TPB+HALO-1
    const int lim  = T_DIM - 1 - t0;
    const int idxl = min(lt + N_STEPS - 1, lim);
    const float gi = expf((float)(t0 + idxl) * LN_GAMMA);  // gamma^idx (absolute)
    float4 nv = s_nq[idxl];

    // Q_WEIGHTS = [1, 0.5, 0, 2]; inv_qw = [1, 2, 0, 0.5]
    float tt0 = rescale_f(rs0 + gi * nv.x + lps * 1.0f);
    float tt1 = rescale_f(rs1 + gi * nv.y + lps * 2.0f);
    float tt3 = rescale_f(rs3 + gi * nv.w + lps * 0.5f);

    float e0 = c4.x - tt0;
    float e1 = c4.y - tt1;
    float e3 = c4.w - tt3;

    float4 o;
    o.x = 0.5f * m * e0 * e0;
    o.y = 0.25f * m * e1 * e1;
    o.z = 0.0f;                       // q_w = 0 -> exactly 0
    o.w = m * e3 * e3;

    ((float4*)out)[bt] = o;
}

extern "C" void kernel_launch(void* const* d_in, const int* in_sizes, int n_in,
                              void* d_out, int out_size)
{
    // metadata order: current_q_value, next_q_value, log_p, reward, is_done, mask
    const float* cq   = (const float*)d_in[0];
    const float* nq   = (const float*)d_in[1];
    const float* logp = (const float*)d_in[2];
    const float* rw   = (const float*)d_in[3];
    const float* done = (const float*)d_in[4];
    const float* mask = (const float*)d_in[5];
    float* out = (float*)d_out;

    int B = in_sizes[2] / T_DIM;   // log_p has B*T elements
    dim3 grid(B, T_DIM / TPB);
    nstep_qloss_kernel<<<grid, TPB>>>(cq, nq, logp, rw, done, mask, out);
}

// round 3
// speedup vs baseline: 1.1197x; 1.1197x over previous
#include <cuda_runtime.h>

#define T_DIM 512
#define N_STEPS 5

__device__ __forceinline__ float sgnf(float x) {
    return (x > 0.0f) ? 1.0f : ((x < 0.0f) ? -1.0f : 0.0f);
}

__device__ __forceinline__ float rescale_f(float x) {
    const float EPS = 1e-3f;
    return sgnf(x) * (sqrtf(fabsf(x) + 1.0f) - 1.0f) + EPS * x;
}

__device__ __forceinline__ float inv_rescale_f(float x) {
    const float EPS = 1e-3f;
    float sqrt_arg = 1.0f + 4.0f * EPS * (fabsf(x) + 1.0f + EPS);
    float r = (sqrtf(sqrt_arg) - 1.0f) / (2.0f * EPS);
    return sgnf(x) * (r * r - 1.0f);
}

__global__ __launch_bounds__(T_DIM)
void nstep_qloss_kernel(const float* __restrict__ cq,
                        const float* __restrict__ nq,
                        const float* __restrict__ logp,
                        const float* __restrict__ rw,
                        const float* __restrict__ done,
                        const float* __restrict__ mask,
                        float* __restrict__ out)
{
    // A[t] = m*reward + gamma*inv_qw*(md*logp/3), zero-padded 4 past the end
    __shared__ float4 s_A[T_DIM + N_STEPS - 1];
    __shared__ float4 s_nq[T_DIM];

    const float GAMMA = 0.997f;
    const float LN_GAMMA = -0.003004509021390342f; // ln(0.997)

    const int b = blockIdx.x;
    const int t = threadIdx.x;
    const long bt = (long)b * T_DIM + t;

    // hoist all global loads (max MLP before barrier)
    float4 c4  = ((const float4*)cq)[bt];
    float  m   = mask[bt];
    float  d   = done[bt];
    float  lpv = logp[bt];
    float4 r4  = ((const float4*)rw)[bt];
    float4 n4  = ((const float4*)nq)[bt];

    const float md = m * (1.0f - d);
    // (gamma/3) * md * lp, per-lane scaled by inv_qw = [1, 2, 0, 0.5]
    const float lpb = (GAMMA / 3.0f) * md * lpv;

    float4 A;
    A.x = fmaf(m, r4.x, lpb * 1.0f);
    A.y = fmaf(m, r4.y, lpb * 2.0f);
    A.z = m * r4.z;                       // inv_qw = 0
    A.w = fmaf(m, r4.w, lpb * 0.5f);
    s_A[t] = A;
    if (t < N_STEPS - 1)
        s_A[T_DIM + t] = make_float4(0.f, 0.f, 0.f, 0.f);

    s_nq[t] = make_float4(md * inv_rescale_f(n4.x),
                          md * inv_rescale_f(n4.y),
                          md * inv_rescale_f(n4.z),
                          md * inv_rescale_f(n4.w));
    __syncthreads();

    // fused window sum: rs_q + inv_qw_q * lps, weights gamma^n
    float rs0 = 0.f, rs1 = 0.f, rs2 = 0.f, rs3 = 0.f;
    float g = 1.0f;
    #pragma unroll
    for (int n = 0; n < N_STEPS; n++) {
        float4 v = s_A[t + n];
        rs0 = fmaf(g, v.x, rs0);
        rs1 = fmaf(g, v.y, rs1);
        rs2 = fmaf(g, v.z, rs2);
        rs3 = fmaf(g, v.w, rs3);
        g *= GAMMA;
    }

    const int idx = min(T_DIM - 1, t + N_STEPS - 1);
    const float gi = expf((float)idx * LN_GAMMA);   // gamma^idx (absolute, per reference)
    float4 nv = s_nq[idx];

    // Q_WEIGHTS = [1, 0.5, 0, 2]
    float tt0 = rescale_f(fmaf(gi, nv.x, rs0));
    float tt1 = rescale_f(fmaf(gi, nv.y, rs1));
    float tt3 = rescale_f(fmaf(gi, nv.w, rs3));
    (void)rs2;

    float e0 = c4.x - tt0;
    float e1 = c4.y - tt1;
    float e3 = c4.w - tt3;

    float4 o;
    o.x = 0.5f  * m * e0 * e0;
    o.y = 0.25f * m * e1 * e1;
    o.z = 0.0f;                         // q_w = 0
    o.w = m * e3 * e3;

    ((float4*)out)[bt] = o;
}

extern "C" void kernel_launch(void* const* d_in, const int* in_sizes, int n_in,
                              void* d_out, int out_size)
{
    // metadata order: current_q_value, next_q_value, log_p, reward, is_done, mask
    const float* cq   = (const float*)d_in[0];
    const float* nq   = (const float*)d_in[1];
    const float* logp = (const float*)d_in[2];
    const float* rw   = (const float*)d_in[3];
    const float* done = (const float*)d_in[4];
    const float* mask = (const float*)d_in[5];
    float* out = (float*)d_out;

    int B = in_sizes[2] / T_DIM;   // log_p has B*T elements
    nstep_qloss_kernel<<<B, T_DIM>>>(cq, nq, logp, rw, done, mask, out);
}

// round 4
// speedup vs baseline: 1.2013x; 1.0729x over previous
#include <cuda_runtime.h>

#define T_DIM 512
#define TPB   256
#define N_STEPS 5

__device__ __forceinline__ float sgnf(float x) {
    return (x > 0.0f) ? 1.0f : ((x < 0.0f) ? -1.0f : 0.0f);
}

__device__ __forceinline__ float rescale_f(float x) {
    const float EPS = 1e-3f;
    return sgnf(x) * (sqrtf(fabsf(x) + 1.0f) - 1.0f) + EPS * x;
}

__device__ __forceinline__ float inv_rescale_f(float x) {
    const float EPS = 1e-3f;
    float sqrt_arg = 1.0f + 4.0f * EPS * (fabsf(x) + 1.0f + EPS);
    float r = (sqrtf(sqrt_arg) - 1.0f) / (2.0f * EPS);
    return sgnf(x) * (r * r - 1.0f);
}

__global__ __launch_bounds__(TPB)
void nstep_qloss_kernel(const float* __restrict__ cq,
                        const float* __restrict__ nq,
                        const float* __restrict__ logp,
                        const float* __restrict__ rw,
                        const float* __restrict__ done,
                        const float* __restrict__ mask,
                        float* __restrict__ out)
{
    // A[t] = m*reward + gamma*inv_qw*(md*logp/3); z lane unused (stored 0)
    __shared__ float4 s_A[T_DIM + N_STEPS - 1];
    __shared__ float4 s_nq[T_DIM];

    const float GAMMA  = 0.997f;
    const float GAMMA2 = 0.997f * 0.997f;
    const float GAMMA3 = GAMMA2 * 0.997f;
    const float GAMMA4 = GAMMA3 * 0.997f;
    const float GAMMA5 = GAMMA4 * 0.997f;
    const float LN_GAMMA = -0.003004509021390342f; // ln(0.997)

    const int b   = blockIdx.x;
    const int l   = threadIdx.x;
    const int t0  = 2 * l;
    const int bt0 = b * T_DIM + t0;        // float4-unit index for Q=4 streams
    const int sc  = b * TPB + l;           // float2-unit index for scalar streams

    // ---- hoisted global loads ----
    float4 c0 = ((const float4*)cq)[bt0];
    float4 c1 = ((const float4*)cq)[bt0 + 1];
    float2 m2 = ((const float2*)mask)[sc];
    float2 d2 = ((const float2*)done)[sc];
    float2 p2 = ((const float2*)logp)[sc];
    float4 r0 = ((const float4*)rw)[bt0];
    float4 r1 = ((const float4*)rw)[bt0 + 1];
    float4 n0 = ((const float4*)nq)[bt0];
    float4 n1 = ((const float4*)nq)[bt0 + 1];

    const float md0 = m2.x * (1.0f - d2.x);
    const float md1 = m2.y * (1.0f - d2.y);
    const float lb0 = (GAMMA / 3.0f) * md0 * p2.x;   // per-lane *inv_qw = [1,2,-,0.5]
    const float lb1 = (GAMMA / 3.0f) * md1 * p2.y;

    float4 a0, a1;
    a0.x = fmaf(m2.x, r0.x, lb0);
    a0.y = fmaf(m2.x, r0.y, 2.0f * lb0);
    a0.z = 0.0f;
    a0.w = fmaf(m2.x, r0.w, 0.5f * lb0);
    a1.x = fmaf(m2.y, r1.x, lb1);
    a1.y = fmaf(m2.y, r1.y, 2.0f * lb1);
    a1.z = 0.0f;
    a1.w = fmaf(m2.y, r1.w, 0.5f * lb1);
    s_A[t0]     = a0;
    s_A[t0 + 1] = a1;
    if (l < 2) {
        s_A[T_DIM + 2 * l]     = make_float4(0.f, 0.f, 0.f, 0.f);
        s_A[T_DIM + 2 * l + 1] = make_float4(0.f, 0.f, 0.f, 0.f);
    }

    float4 q0, q1;   // md * inv_rescale(next_q), z lane dead
    q0.x = md0 * inv_rescale_f(n0.x);
    q0.y = md0 * inv_rescale_f(n0.y);
    q0.z = 0.0f;
    q0.w = md0 * inv_rescale_f(n0.w);
    q1.x = md1 * inv_rescale_f(n1.x);
    q1.y = md1 * inv_rescale_f(n1.y);
    q1.z = 0.0f;
    q1.w = md1 * inv_rescale_f(n1.w);
    s_nq[t0]     = q0;
    s_nq[t0 + 1] = q1;
    __syncthreads();

    // window values A[t0+2 .. t0+5] from shared; A[t0], A[t0+1] in regs
    float4 A2 = s_A[t0 + 2];
    float4 A3 = s_A[t0 + 3];
    float4 A4 = s_A[t0 + 4];
    float4 A5 = s_A[t0 + 5];

    // rs1 = sum_{n=0..4} gamma^n A[t0+1+n]
    float rs1x = fmaf(GAMMA4, A5.x, fmaf(GAMMA3, A4.x, fmaf(GAMMA2, A3.x, fmaf(GAMMA, A2.x, a1.x))));
    float rs1y = fmaf(GAMMA4, A5.y, fmaf(GAMMA3, A4.y, fmaf(GAMMA2, A3.y, fmaf(GAMMA, A2.y, a1.y))));
    float rs1w = fmaf(GAMMA4, A5.w, fmaf(GAMMA3, A4.w, fmaf(GAMMA2, A3.w, fmaf(GAMMA, A2.w, a1.w))));
    // rs0 = A[t0] + gamma*rs1 - gamma^5 * A[t0+5]
    float rs0x = fmaf(GAMMA, rs1x, fmaf(-GAMMA5, A5.x, a0.x));
    float rs0y = fmaf(GAMMA, rs1y, fmaf(-GAMMA5, A5.y, a0.y));
    float rs0w = fmaf(GAMMA, rs1w, fmaf(-GAMMA5, A5.w, a0.w));

    const int idx0 = min(T_DIM - 1, t0 + 4);
    const int idx1 = min(T_DIM - 1, t0 + 5);
    const float gi0 = expf((float)idx0 * LN_GAMMA);          // gamma^idx (absolute)
    const float gi1 = (idx1 == idx0) ? gi0 : gi0 * GAMMA;
    float4 v0 = s_nq[idx0];
    float4 v1 = s_nq[idx1];

    // Q_WEIGHTS = [1, 0.5, 0, 2]
    float e0x = c0.x - rescale_f(fmaf(gi0, v0.x, rs0x));
    float e0y = c0.y - rescale_f(fmaf(gi0, v0.y, rs0y));
    float e0w = c0.w - rescale_f(fmaf(gi0, v0.w, rs0w));
    float e1x = c1.x - rescale_f(fmaf(gi1, v1.x, rs1x));
    float e1y = c1.y - rescale_f(fmaf(gi1, v1.y, rs1y));
    float e1w = c1.w - rescale_f(fmaf(gi1, v1.w, rs1w));

    float4 o0, o1;
    o0.x = 0.5f  * m2.x * e0x * e0x;
    o0.y = 0.25f * m2.x * e0y * e0y;
    o0.z = 0.0f;
    o0.w = m2.x * e0w * e0w;
    o1.x = 0.5f  * m2.y * e1x * e1x;
    o1.y = 0.25f * m2.y * e1y * e1y;
    o1.z = 0.0f;
    o1.w = m2.y * e1w * e1w;

    ((float4*)out)[bt0]     = o0;
    ((float4*)out)[bt0 + 1] = o1;
}

extern "C" void kernel_launch(void* const* d_in, const int* in_sizes, int n_in,
                              void* d_out, int out_size)
{
    // metadata order: current_q_value, next_q_value, log_p, reward, is_done, mask
    const float* cq   = (const float*)d_in[0];
    const float* nq   = (const float*)d_in[1];
    const float* logp = (const float*)d_in[2];
    const float* rw   = (const float*)d_in[3];
    const float* done = (const float*)d_in[4];
    const float* mask = (const float*)d_in[5];
    float* out = (float*)d_out;

    int B = in_sizes[2] / T_DIM;   // log_p has B*T elements
    nstep_qloss_kernel<<<B, TPB>>>(cq, nq, logp, rw, done, mask, out);
}

// round 5
// speedup vs baseline: 1.2119x; 1.0088x over previous
#include <cuda_runtime.h>

#define T_DIM 512
#define TPB   256
#define N_STEPS 5

__device__ __forceinline__ float sgnf(float x) {
    return (x > 0.0f) ? 1.0f : ((x < 0.0f) ? -1.0f : 0.0f);
}

__device__ __forceinline__ float rescale_f(float x) {
    const float EPS = 1e-3f;
    return sgnf(x) * (sqrtf(fabsf(x) + 1.0f) - 1.0f) + EPS * x;
}

__device__ __forceinline__ float inv_rescale_f(float x) {
    const float EPS = 1e-3f;
    float sqrt_arg = 1.0f + 4.0f * EPS * (fabsf(x) + 1.0f + EPS);
    float r = (sqrtf(sqrt_arg) - 1.0f) / (2.0f * EPS);
    return sgnf(x) * (r * r - 1.0f);
}

__global__ __launch_bounds__(TPB)
void nstep_qloss_kernel(const float* __restrict__ cq,
                        const float* __restrict__ nq,
                        const float* __restrict__ logp,
                        const float* __restrict__ rw,
                        const float* __restrict__ done,
                        const float* __restrict__ mask,
                        float* __restrict__ out)
{
    // Only A is staged in shared: A[t] = m*reward + gamma*inv_qw*(md*logp/3)
    __shared__ float4 s_A[T_DIM + N_STEPS - 1];

    const float GAMMA  = 0.997f;
    const float GAMMA2 = 0.997f * 0.997f;
    const float GAMMA3 = GAMMA2 * 0.997f;
    const float GAMMA4 = GAMMA3 * 0.997f;
    const float GAMMA5 = GAMMA4 * 0.997f;
    const float LN_GAMMA = -0.003004509021390342f; // ln(0.997)

    const int b   = blockIdx.x;
    const int l   = threadIdx.x;
    const int t0  = 2 * l;
    const int row = b * T_DIM;
    const int bt0 = row + t0;              // float4-unit index for Q=4 streams
    const int sc  = b * TPB + l;           // float2-unit index for scalar streams

    // gathered indices (clamped at row end; last 2 threads broadcast-read 511)
    const int idx0 = min(T_DIM - 1, t0 + 4);
    const int idx1 = min(T_DIM - 1, t0 + 5);

    // ---- hoisted global loads (max MLP) ----
    float4 c0 = ((const float4*)cq)[bt0];
    float4 c1 = ((const float4*)cq)[bt0 + 1];
    float2 m2 = ((const float2*)mask)[sc];
    float2 d2 = ((const float2*)done)[sc];
    float2 p2 = ((const float2*)logp)[sc];
    float4 r0 = ((const float4*)rw)[bt0];
    float4 r1 = ((const float4*)rw)[bt0 + 1];
    // shifted (gathered) streams loaded directly from global — no staging
    float  mi0 = mask[row + idx0];
    float  mi1 = mask[row + idx1];
    float  di0 = done[row + idx0];
    float  di1 = done[row + idx1];
    float4 n0  = ((const float4*)nq)[row + idx0];
    float4 n1  = ((const float4*)nq)[row + idx1];

    const float md0 = m2.x * (1.0f - d2.x);
    const float md1 = m2.y * (1.0f - d2.y);
    const float lb0 = (GAMMA / 3.0f) * md0 * p2.x;   // per-lane *inv_qw = [1,2,-,0.5]
    const float lb1 = (GAMMA / 3.0f) * md1 * p2.y;

    float4 a0, a1;
    a0.x = fmaf(m2.x, r0.x, lb0);
    a0.y = fmaf(m2.x, r0.y, 2.0f * lb0);
    a0.z = 0.0f;
    a0.w = fmaf(m2.x, r0.w, 0.5f * lb0);
    a1.x = fmaf(m2.y, r1.x, lb1);
    a1.y = fmaf(m2.y, r1.y, 2.0f * lb1);
    a1.z = 0.0f;
    a1.w = fmaf(m2.y, r1.w, 0.5f * lb1);
    s_A[t0]     = a0;
    s_A[t0 + 1] = a1;
    if (l < 2) {
        s_A[T_DIM + 2 * l]     = make_float4(0.f, 0.f, 0.f, 0.f);
        s_A[T_DIM + 2 * l + 1] = make_float4(0.f, 0.f, 0.f, 0.f);
    }

    // gathered next-q term computed directly in registers
    const float mdi0 = mi0 * (1.0f - di0);
    const float mdi1 = mi1 * (1.0f - di1);
    float v0x = mdi0 * inv_rescale_f(n0.x);
    float v0y = mdi0 * inv_rescale_f(n0.y);
    float v0w = mdi0 * inv_rescale_f(n0.w);
    float v1x = mdi1 * inv_rescale_f(n1.x);
    float v1y = mdi1 * inv_rescale_f(n1.y);
    float v1w = mdi1 * inv_rescale_f(n1.w);

    __syncthreads();

    // window values A[t0+2 .. t0+5] from shared; A[t0], A[t0+1] in regs
    float4 A2 = s_A[t0 + 2];
    float4 A3 = s_A[t0 + 3];
    float4 A4 = s_A[t0 + 4];
    float4 A5 = s_A[t0 + 5];

    // rs1 = sum_{n=0..4} gamma^n A[t0+1+n]
    float rs1x = fmaf(GAMMA4, A5.x, fmaf(GAMMA3, A4.x, fmaf(GAMMA2, A3.x, fmaf(GAMMA, A2.x, a1.x))));
    float rs1y = fmaf(GAMMA4, A5.y, fmaf(GAMMA3, A4.y, fmaf(GAMMA2, A3.y, fmaf(GAMMA, A2.y, a1.y))));
    float rs1w = fmaf(GAMMA4, A5.w, fmaf(GAMMA3, A4.w, fmaf(GAMMA2, A3.w, fmaf(GAMMA, A2.w, a1.w))));
    // rs0 = A[t0] + gamma*rs1 - gamma^5 * A[t0+5]
    float rs0x = fmaf(GAMMA, rs1x, fmaf(-GAMMA5, A5.x, a0.x));
    float rs0y = fmaf(GAMMA, rs1y, fmaf(-GAMMA5, A5.y, a0.y));
    float rs0w = fmaf(GAMMA, rs1w, fmaf(-GAMMA5, A5.w, a0.w));

    const float gi0 = expf((float)idx0 * LN_GAMMA);          // gamma^idx (absolute)
    const float gi1 = (idx1 == idx0) ? gi0 : gi0 * GAMMA;

    // Q_WEIGHTS = [1, 0.5, 0, 2]
    float e0x = c0.x - rescale_f(fmaf(gi0, v0x, rs0x));
    float e0y = c0.y - rescale_f(fmaf(gi0, v0y, rs0y));
    float e0w = c0.w - rescale_f(fmaf(gi0, v0w, rs0w));
    float e1x = c1.x - rescale_f(fmaf(gi1, v1x, rs1x));
    float e1y = c1.y - rescale_f(fmaf(gi1, v1y, rs1y));
    float e1w = c1.w - rescale_f(fmaf(gi1, v1w, rs1w));

    float4 o0, o1;
    o0.x = 0.5f  * m2.x * e0x * e0x;
    o0.y = 0.25f * m2.x * e0y * e0y;
    o0.z = 0.0f;
    o0.w = m2.x * e0w * e0w;
    o1.x = 0.5f  * m2.y * e1x * e1x;
    o1.y = 0.25f * m2.y * e1y * e1y;
    o1.z = 0.0f;
    o1.w = m2.y * e1w * e1w;

    ((float4*)out)[bt0]     = o0;
    ((float4*)out)[bt0 + 1] = o1;
}

extern "C" void kernel_launch(void* const* d_in, const int* in_sizes, int n_in,
                              void* d_out, int out_size)
{
    // metadata order: current_q_value, next_q_value, log_p, reward, is_done, mask
    const float* cq   = (const float*)d_in[0];
    const float* nq   = (const float*)d_in[1];
    const float* logp = (const float*)d_in[2];
    const float* rw   = (const float*)d_in[3];
    const float* done = (const float*)d_in[4];
    const float* mask = (const float*)d_in[5];
    float* out = (float*)d_out;

    int B = in_sizes[2] / T_DIM;   // log_p has B*T elements
    nstep_qloss_kernel<<<B, TPB>>>(cq, nq, logp, rw, done, mask, out);
}